// round 3
// baseline (speedup 1.0000x reference)
#include <cuda_runtime.h>
#include <cuda_fp16.h>
#include <math.h>

#define NG 192
#define BX 32
#define BY 4
#define BZ 4
#define TX (BX + 4)      // 36
#define TY (BY + 4)      // 8
#define TZ (BZ + 4)      // 8
#define TILE (TX * TY * TZ)   // 2304
#define TXH TX                 // pair-entries per row (entry c covers cols c, c+1)
#define HTILE (TZ * TY * TXH)  // 2304
#define NTOT (NG * NG * NG)

#define KN   500000.0f
#define MU   0.5f
#define EPSF 1e-4f
#define FULLMASK 0xffffffffu

__device__ __forceinline__ int wrapN(int v) {
    if (v < 0) v += NG;
    if (v >= NG) v -= NG;
    return v;
}

__device__ __forceinline__ __half2 pair_r2(uint2 q, __half2 pxh2, __half2 pyh2) {
    __half2 hx = *reinterpret_cast<__half2*>(&q.x);
    __half2 hy = *reinterpret_cast<__half2*>(&q.y);
    __half2 dx = __hsub2(pxh2, hx);
    __half2 dy = __hsub2(pyh2, hy);
    return __hfma2(dy, dy, __hmul2(dx, dx));
}

__global__ __launch_bounds__(BX * BY * BZ)
void dem_kernel(const float* __restrict__ xg, const float* __restrict__ yg,
                const float* __restrict__ zg, const float* __restrict__ vxg,
                const float* __restrict__ vyg, const float* __restrict__ vzg,
                const float* __restrict__ dptr, float* __restrict__ out,
                float eta)
{
    __shared__ float2 sxy[TILE];      // exact fp32 (x,y) for fallback
    __shared__ float  szs[TILE];      // exact fp32 z
    __shared__ uint2  hpk[HTILE];     // packed half2 {x_c,x_c+1}, {y_c,y_c+1}

    const int lx = threadIdx.x, ly = threadIdx.y, lz = threadIdx.z;
    const int bx0 = blockIdx.x * BX;
    const int by0 = blockIdx.y * BY;
    const int bz0 = blockIdx.z * BZ;
    const int tid = (lz * BY + ly) * BX + lx;

    // --- phase 1: cooperative halo load (wraparound) ---
    for (int idx = tid; idx < TILE; idx += BX * BY * BZ) {
        int txi = idx % TX;
        int rem = idx / TX;
        int tyi = rem % TY;
        int tzi = rem / TY;
        int gx = wrapN(bx0 + txi - 2);
        int gy = wrapN(by0 + tyi - 2);
        int gz = wrapN(bz0 + tzi - 2);
        int g = (gz * NG + gy) * NG + gx;
        sxy[idx] = make_float2(xg[g], yg[g]);
        szs[idx] = zg[g];
    }
    __syncthreads();

    // --- phase 2: build packed half2 pair table from smem ---
    for (int idx = tid; idx < HTILE; idx += BX * BY * BZ) {
        int c = idx % TXH;
        int r = idx / TXH;
        float2 a = sxy[r * TX + c];
        float2 b = (c + 1 < TX) ? sxy[r * TX + c + 1]
                                : make_float2(16384.f, 16384.f); // dummy: always fails
        __half2 hx = __floats2half2_rn(a.x, b.x);
        __half2 hy = __floats2half2_rn(a.y, b.y);
        uint2 u;
        u.x = *reinterpret_cast<unsigned*>(&hx);
        u.y = *reinterpret_cast<unsigned*>(&hy);
        hpk[idx] = u;
    }
    __syncthreads();

    const float d      = *dptr;
    const float two_d  = 2.0f * d;
    const float two_d2 = two_d * two_d;
    // conservative half-precision prefilter threshold:
    // true hit => |dx|,|dy| < two_d; half repr error <= 0.0625/coord
    // => r2_half <= 2*(two_d+0.13)^2*(1+eps). Use margin 0.15 + 0.02 abs.
    const float thrf = 2.0f * (two_d + 0.15f) * (two_d + 0.15f) + 0.02f;
    const __half2 thr2 = __float2half2_rn(thrf);

    const int cz = lz + 2, cy = ly + 2, cx = lx + 2;
    const int cidx = (cz * TY + cy) * TX + cx;
    const float2 pxy = sxy[cidx];
    const float px = pxy.x, py = pxy.y, pz = szs[cidx];
    const __half2 pxh2 = __float2half2_rn(px);
    const __half2 pyh2 = __float2half2_rn(py);

    const int ga = bz0 + lz, gb = by0 + ly, gc = bx0 + lx;
    const int gidx = (ga * NG + gb) * NG + gc;

    const float pvx = vxg[gidx], pvy = vyg[gidx], pvz = vzg[gidx];

    float fxc = 0.f, fyc = 0.f, fzc = 0.f;
    float fxd = 0.f, fyd = 0.f, fzd = 0.f;

    const __half hbig = __ushort_as_half(0x7bff);  // 65504, max finite half

    #pragma unroll
    for (int oz = -2; oz <= 2; oz++) {
        #pragma unroll
        for (int oy = -2; oy <= 2; oy++) {
            // packed prefilter: 3 LDS.64 cover columns cx-2 .. cx+3
            const int ro = ((cz + oz) * TY + (cy + oy)) * TXH + (cx - 2);
            uint2 q0 = hpk[ro];
            uint2 q1 = hpk[ro + 2];
            uint2 q2 = hpk[ro + 4];
            __half2 r20 = pair_r2(q0, pxh2, pyh2);
            __half2 r21 = pair_r2(q1, pxh2, pyh2);
            __half2 r22 = pair_r2(q2, pxh2, pyh2);
            if (oz == 0 && oy == 0) {
                // mask the self pair (col cx = low half of q1): r2 = 0 always
                r21 = __halves2half2(hbig, __high2half(r21));
            }
            __half2 rmin = __hmin2(__hmin2(r20, r21), r22);
            // at least one of the two halves below threshold?
            const bool pre = !__hbge2(rmin, thr2);
            if (__any_sync(FULLMASK, pre)) {        // ~3.5% of rows
                // exact fp32 fallback for this row's 5 offsets
                const int rb = ((cz + oz) * TY + (cy + oy)) * TX + cx;
                #pragma unroll
                for (int ox = -2; ox <= 2; ox++) {
                    const float2 nxy = sxy[rb + ox];
                    const float dx = px - nxy.x;
                    const float dy = py - nxy.y;
                    const float dz = pz - szs[rb + ox];
                    const float d2 = fmaf(dz, dz, fmaf(dy, dy, dx * dx));
                    const bool hit = (d2 < two_d2) && (d2 > 0.0f);
                    if (__any_sync(FULLMASK, hit)) { // essentially never
                        if (hit) {
                            const float dist = sqrtf(d2);
                            const float safe = fmaxf(EPSF, dist);
                            const float inv  = 1.0f / safe;
                            const float coef = KN * (dist - two_d) * inv;
                            fxc += coef * dx;
                            fyc += coef * dy;
                            fzc += coef * dz;
                            const int na = wrapN(ga + oz);
                            const int nb = wrapN(gb + oy);
                            const int nc = wrapN(gc + ox);
                            const int nidx = (na * NG + nb) * NG + nc;
                            const float dvx = pvx - vxg[nidx];
                            const float dvy = pvy - vyg[nidx];
                            const float dvz = pvz - vzg[nidx];
                            const float vn  = (dvx * dx + dvy * dy + dvz * dz) * inv;
                            const float c2  = eta * vn * inv;
                            fxd += c2 * dx;
                            fyd += c2 * dy;
                            fzd += c2 * dz;
                        }
                    }
                }
            }
        }
    }

    // --- friction: only the LAST scan shift s=(2,2,2) survives, i.e.
    //     neighbor offset (-2,-2,-2), against the fully accumulated sums. ---
    float frx = 0.f, fry = 0.f, frz = 0.f;
    {
        const int rb = ((cz - 2) * TY + (cy - 2)) * TX + (cx - 2);
        const float2 nxy = sxy[rb];
        const float dx = px - nxy.x;
        const float dy = py - nxy.y;
        const float r2 = fmaf(dy, dy, dx * dx);
        if (__any_sync(FULLMASK, r2 < two_d2)) {
            const float dz = pz - szs[rb];
            const float d2 = fmaf(dz, dz, r2);
            if (d2 < two_d2) {
                const int na = wrapN(ga - 2);
                const int nb = wrapN(gb - 2);
                const int nc = wrapN(gc - 2);
                const int nidx = (na * NG + nb) * NG + nc;
                const float dvx = pvx - vxg[nidx];
                const float dvy = pvy - vyg[nidx];
                const float dvz = pvz - vzg[nidx];
                frx = -(fabsf(fabsf(MU * fyc) + fabsf(MU * fzc) - MU * fxd)
                        * dvx / fmaxf(EPSF, fabsf(dvx)));
                fry = -(fabsf(fabsf(MU * fxc) + fabsf(MU * fzc) - MU * fyd)
                        * dvy / fmaxf(EPSF, fabsf(dvy)));
                // NB: reference uses diffvy in the z-friction numerator (kept).
                frz = -(fabsf(fabsf(MU * fxc) + fabsf(MU * fyc) - MU * fzd)
                        * dvy / fmaxf(EPSF, fabsf(dvz)));
            }
        }
    }

    out[0 * NTOT + gidx] = fxc;
    out[1 * NTOT + gidx] = fyc;
    out[2 * NTOT + gidx] = fzc;
    out[3 * NTOT + gidx] = fxd;
    out[4 * NTOT + gidx] = fyd;
    out[5 * NTOT + gidx] = fzd;
    out[6 * NTOT + gidx] = frx;
    out[7 * NTOT + gidx] = fry;
    out[8 * NTOT + gidx] = frz;
}

extern "C" void kernel_launch(void* const* d_in, const int* in_sizes, int n_in,
                              void* d_out, int out_size)
{
    const float* xg   = (const float*)d_in[0];
    const float* yg   = (const float*)d_in[1];
    const float* zg   = (const float*)d_in[2];
    const float* vxg  = (const float*)d_in[3];
    const float* vyg  = (const float*)d_in[4];
    const float* vzg  = (const float*)d_in[5];
    const float* dptr = (const float*)d_in[6];
    float* out = (float*)d_out;

    // ETA = 2*gamma*sqrt(KN), gamma = alpha/sqrt(alpha^2+1), alpha = -ln(0.7)/pi
    const double alpha = -log(0.7) / M_PI;
    const double gam   = alpha / sqrt(alpha * alpha + 1.0);
    const float  eta   = (float)(2.0 * gam * sqrt(500000.0));

    dim3 block(BX, BY, BZ);
    dim3 grid(NG / BX, NG / BY, NG / BZ);
    dem_kernel<<<grid, block>>>(xg, yg, zg, vxg, vyg, vzg, dptr, out, eta);
}

// round 4
// speedup vs baseline: 1.9285x; 1.9285x over previous
#include <cuda_runtime.h>
#include <math.h>

#define NG 192
#define BX 32
#define BY 4
#define BZ 4
#define TX (BX + 4)      // 36
#define TY (BY + 4)      // 8
#define TZ (BZ + 4)      // 8
#define TILE (TX * TY * TZ)   // 2304
#define NTOT (NG * NG * NG)

#define KN   500000.0f
#define MU   0.5f
#define EPSF 1e-4f
#define FULLMASK 0xffffffffu

__device__ __forceinline__ int wrapN(int v) {
    if (v < 0) v += NG;
    if (v >= NG) v -= NG;
    return v;
}

__global__ __launch_bounds__(BX * BY * BZ)
void dem_kernel(const float* __restrict__ xg, const float* __restrict__ yg,
                const float* __restrict__ zg, const float* __restrict__ vxg,
                const float* __restrict__ vyg, const float* __restrict__ vzg,
                const float* __restrict__ dptr, float* __restrict__ out,
                float eta)
{
    __shared__ float2   sxy[TILE];   // exact fp32 (x,y) for fallback + friction
    __shared__ float    szs[TILE];   // exact fp32 z
    __shared__ unsigned qpk[TILE];   // bytes: (floor(x), floor(y), floor(z), 0)

    const int lx = threadIdx.x, ly = threadIdx.y, lz = threadIdx.z;
    const int bx0 = blockIdx.x * BX;
    const int by0 = blockIdx.y * BY;
    const int bz0 = blockIdx.z * BZ;
    const int tid = (lz * BY + ly) * BX + lx;

    // --- cooperative halo load (wraparound) + quantized key build ---
    for (int idx = tid; idx < TILE; idx += BX * BY * BZ) {
        int txi = idx % TX;
        int rem = idx / TX;
        int tyi = rem % TY;
        int tzi = rem / TY;
        int gx = wrapN(bx0 + txi - 2);
        int gy = wrapN(by0 + tyi - 2);
        int gz = wrapN(bz0 + tzi - 2);
        int g = (gz * NG + gy) * NG + gx;
        float x = xg[g], y = yg[g], z = zg[g];
        sxy[idx] = make_float2(x, y);
        szs[idx] = z;
        // coords in [0, 192): floors fit a byte
        qpk[idx] = (unsigned)(int)x | ((unsigned)(int)y << 8)
                 | ((unsigned)(int)z << 16);
    }
    __syncthreads();

    const float d      = *dptr;
    const float two_d  = 2.0f * d;
    const float two_d2 = two_d * two_d;
    // filter validity: |dx|<two_d<=1  =>  |floor(x)-floor(nx)| <= 1  (per axis)
    const bool filter_ok = (two_d <= 1.0f);

    const int cz = lz + 2, cy = ly + 2, cx = lx + 2;
    const int cidx = (cz * TY + cy) * TX + cx;
    const float2 pxy = sxy[cidx];
    const float px = pxy.x, py = pxy.y, pz = szs[cidx];
    const unsigned pq = qpk[cidx];

    const int ga = bz0 + lz, gb = by0 + ly, gc = bx0 + lx;
    const int gidx = (ga * NG + gb) * NG + gc;

    const float pvx = vxg[gidx], pvy = vyg[gidx], pvz = vzg[gidx];

    float fxc = 0.f, fyc = 0.f, fzc = 0.f;
    float fxd = 0.f, fyd = 0.f, fzd = 0.f;

    // ---- fast prefilter: 4 instr per offset, no branches, one vote ----
    bool need_exact = !filter_ok;
    if (filter_ok) {
        unsigned m0 = 0xffffffffu, m1 = 0xffffffffu;
        unsigned m2 = 0xffffffffu, m3 = 0xffffffffu;
        #pragma unroll
        for (int oz = -2; oz <= 2; oz++) {
            #pragma unroll
            for (int oy = -2; oy <= 2; oy++) {
                #pragma unroll
                for (int ox = -2; ox <= 2; ox++) {
                    if (oz == 0 && oy == 0 && ox == 0) continue; // self: skip
                    const int off = ((cz + oz) * TY + (cy + oy)) * TX + (cx + ox);
                    unsigned nq = qpk[off];
                    unsigned df = __vabsdiffu4(pq, nq);
                    unsigned v  = df & 0x00FEFEFEu;   // ==0 iff all byte diffs <=1
                    // rotate accumulators for ILP
                    int lane = ((oz + 2) * 5 + (oy + 2)) & 3;
                    if (lane == 0)      m0 = min(m0, v);
                    else if (lane == 1) m1 = min(m1, v);
                    else if (lane == 2) m2 = min(m2, v);
                    else                m3 = min(m3, v);
                }
            }
        }
        unsigned m = min(min(m0, m1), min(m2, m3));
        need_exact = (m == 0u);
    }

    // ---- exact fallback (rare: ~1.5% of warps) ----
    if (__any_sync(FULLMASK, need_exact)) {
        #pragma unroll 1
        for (int oz = -2; oz <= 2; oz++) {
            for (int oy = -2; oy <= 2; oy++) {
                const int rb = ((cz + oz) * TY + (cy + oy)) * TX + cx;
                for (int ox = -2; ox <= 2; ox++) {
                    const float2 nxy = sxy[rb + ox];
                    const float dx = px - nxy.x;
                    const float dy = py - nxy.y;
                    const float dz = pz - szs[rb + ox];
                    const float d2 = fmaf(dz, dz, fmaf(dy, dy, dx * dx));
                    // d2 == 0 pairs (incl. self) contribute exactly 0 -> skip
                    const bool hit = (d2 < two_d2) && (d2 > 0.0f);
                    if (hit) {
                        const float dist = sqrtf(d2);
                        const float safe = fmaxf(EPSF, dist);
                        const float inv  = 1.0f / safe;
                        const float coef = KN * (dist - two_d) * inv;
                        fxc += coef * dx;
                        fyc += coef * dy;
                        fzc += coef * dz;
                        const int na = wrapN(ga + oz);
                        const int nb = wrapN(gb + oy);
                        const int nc = wrapN(gc + ox);
                        const int nidx = (na * NG + nb) * NG + nc;
                        const float dvx = pvx - vxg[nidx];
                        const float dvy = pvy - vyg[nidx];
                        const float dvz = pvz - vzg[nidx];
                        const float vn  = (dvx * dx + dvy * dy + dvz * dz) * inv;
                        const float c2  = eta * vn * inv;
                        fxd += c2 * dx;
                        fyd += c2 * dy;
                        fzd += c2 * dz;
                    }
                }
            }
        }
    }

    // --- friction: only the LAST scan shift s=(2,2,2) survives, i.e.
    //     neighbor offset (-2,-2,-2), against the fully accumulated sums. ---
    float frx = 0.f, fry = 0.f, frz = 0.f;
    {
        const int rb = ((cz - 2) * TY + (cy - 2)) * TX + (cx - 2);
        const float2 nxy = sxy[rb];
        const float dx = px - nxy.x;
        const float dy = py - nxy.y;
        const float r2 = fmaf(dy, dy, dx * dx);
        if (__any_sync(FULLMASK, r2 < two_d2)) {
            const float dz = pz - szs[rb];
            const float d2 = fmaf(dz, dz, r2);
            if (d2 < two_d2) {
                const int na = wrapN(ga - 2);
                const int nb = wrapN(gb - 2);
                const int nc = wrapN(gc - 2);
                const int nidx = (na * NG + nb) * NG + nc;
                const float dvx = pvx - vxg[nidx];
                const float dvy = pvy - vyg[nidx];
                const float dvz = pvz - vzg[nidx];
                frx = -(fabsf(fabsf(MU * fyc) + fabsf(MU * fzc) - MU * fxd)
                        * dvx / fmaxf(EPSF, fabsf(dvx)));
                fry = -(fabsf(fabsf(MU * fxc) + fabsf(MU * fzc) - MU * fyd)
                        * dvy / fmaxf(EPSF, fabsf(dvy)));
                // NB: reference uses diffvy in the z-friction numerator (kept).
                frz = -(fabsf(fabsf(MU * fxc) + fabsf(MU * fyc) - MU * fzd)
                        * dvy / fmaxf(EPSF, fabsf(dvz)));
            }
        }
    }

    out[0 * NTOT + gidx] = fxc;
    out[1 * NTOT + gidx] = fyc;
    out[2 * NTOT + gidx] = fzc;
    out[3 * NTOT + gidx] = fxd;
    out[4 * NTOT + gidx] = fyd;
    out[5 * NTOT + gidx] = fzd;
    out[6 * NTOT + gidx] = frx;
    out[7 * NTOT + gidx] = fry;
    out[8 * NTOT + gidx] = frz;
}

extern "C" void kernel_launch(void* const* d_in, const int* in_sizes, int n_in,
                              void* d_out, int out_size)
{
    const float* xg   = (const float*)d_in[0];
    const float* yg   = (const float*)d_in[1];
    const float* zg   = (const float*)d_in[2];
    const float* vxg  = (const float*)d_in[3];
    const float* vyg  = (const float*)d_in[4];
    const float* vzg  = (const float*)d_in[5];
    const float* dptr = (const float*)d_in[6];
    float* out = (float*)d_out;

    // ETA = 2*gamma*sqrt(KN), gamma = alpha/sqrt(alpha^2+1), alpha = -ln(0.7)/pi
    const double alpha = -log(0.7) / M_PI;
    const double gam   = alpha / sqrt(alpha * alpha + 1.0);
    const float  eta   = (float)(2.0 * gam * sqrt(500000.0));

    dim3 block(BX, BY, BZ);
    dim3 grid(NG / BX, NG / BY, NG / BZ);
    dem_kernel<<<grid, block>>>(xg, yg, zg, vxg, vyg, vzg, dptr, out, eta);
}